// round 4
// baseline (speedup 1.0000x reference)
#include <cuda_runtime.h>
#include <math.h>

#define N_SAMPLES 131072
#define N_EVENTS  128
#define N_ATOMS   32
#define ATOM_SIZE 512
#define LATENT    16
#define TIME_DIM  17
#define LAYERS    7

// ---------------- device-global scratch (no allocation allowed) ----------------
__device__ float g_x[2][N_EVENTS * LATENT];          // ping-pong latent buffers
__device__ float g_t[2][N_EVENTS * TIME_DIM * 2];    // ping-pong time buffers
__device__ int   g_pos[N_EVENTS];                    // dirac shift per event
__device__ float g_wave[N_EVENTS * ATOM_SIZE];       // pre-scaled waveforms

// ---------------- K1: binary tree of linear layers + argmax positions ----------
__global__ void tree_kernel(const float* __restrict__ base_latent,
                            const float* __restrict__ Wt,   // (7, 68, 16)
                            const float* __restrict__ Ws,   // (7, 32, 16)
                            const float* __restrict__ bs)   // (7, 32)
{
    const int tid = threadIdx.x;

    if (tid < LATENT)        g_x[0][tid] = base_latent[tid];
    if (tid < TIME_DIM * 2)  g_t[0][tid] = 0.0f;
    __syncthreads();

    for (int i = 0; i < LAYERS; i++) {
        const int n = 1 << i;
        const float* wt = Wt + i * 68 * LATENT;
        const float* ws = Ws + i * 32 * LATENT;
        const float* bb = bs + i * 32;
        const float* xA = g_x[i & 1];
        float*       xB = g_x[(i & 1) ^ 1];
        const float* tA = g_t[i & 1];
        float*       tB = g_t[(i & 1) ^ 1];

        // time offsets: per parent event, 68 outputs -> children times
        for (int idx = tid; idx < n * 68; idx += blockDim.x) {
            const int e = idx / 68, j = idx % 68;
            const int c = j / 34, r = j % 34;     // child, (t*2+s)
            float v = 0.0f;
            #pragma unroll
            for (int d = 0; d < LATENT; d++) v += xA[e * LATENT + d] * wt[j * LATENT + d];
            tB[(2 * e + c) * 34 + r] = tA[e * 34 + r] + v;
        }
        // latent split: per parent event, 32 outputs -> two children of 16
        for (int idx = tid; idx < n * 32; idx += blockDim.x) {
            const int e = idx / 32, j = idx % 32;
            float v = bb[j];
            #pragma unroll
            for (int d = 0; d < LATENT; d++) v += xA[e * LATENT + d] * ws[j * LATENT + d];
            xB[(2 * e + (j >> 4)) * LATENT + (j & 15)] = v;
        }
        __syncthreads();   // single block: orders global writes/reads across layers
    }

    // final buffers live in parity 1 (LAYERS=7 is odd)
    const float* tF = g_t[1];
    for (int e = tid; e < N_EVENTS; e += blockDim.x) {
        int p = 0;
        #pragma unroll
        for (int t = 0; t < TIME_DIM; t++) {
            // argmax over size-2 axis; ties -> index 0 (strict >)
            const int bit = tF[e * 34 + t * 2 + 1] > tF[e * 34 + t * 2 + 0];
            p |= bit << (TIME_DIM - 1 - t);
        }
        g_pos[e] = p;
    }
}

// ---------------- K2: per-event waveform (coeffs, window, norm, amp) -----------
__global__ void wave_kernel(const float* __restrict__ atoms,   // (32, 512)
                            const float* __restrict__ Wa,      // (32, 16)
                            const float* __restrict__ ba,      // (32,)
                            const float* __restrict__ Wamp,    // (1, 16)
                            const float* __restrict__ bamp)    // (1,)
{
    __shared__ float cs[N_ATOMS];
    __shared__ float s_amp;
    __shared__ float s_red[4];

    const int e   = blockIdx.x;
    const int tid = threadIdx.x;          // 128 threads
    const float* xe = g_x[1] + e * LATENT;

    if (tid < N_ATOMS) {
        float v = ba[tid];
        #pragma unroll
        for (int d = 0; d < LATENT; d++) v += xe[d] * Wa[tid * LATENT + d];
        cs[tid] = v;
    }
    if (tid == N_ATOMS) {
        float v = bamp[0];
        #pragma unroll
        for (int d = 0; d < LATENT; d++) v += xe[d] * Wamp[d];
        s_amp = v;
    }
    __syncthreads();

    float w[4];
    float sq = 0.0f;
    #pragma unroll
    for (int q = 0; q < 4; q++) {
        const int j = tid + q * 128;
        float v = 0.0f;
        #pragma unroll
        for (int k = 0; k < N_ATOMS; k++) v += cs[k] * atoms[k * ATOM_SIZE + j];
        // Hamming window: 0.54 - 0.46*cos(2*pi*j/512) = 0.54 - 0.46*cos(pi*(j/256))
        const float win = 0.54f - 0.46f * cospif((float)j * (1.0f / 256.0f));
        v *= win;
        w[q] = v;
        sq += v * v;
    }

    // block reduce sum of squares (4 warps)
    #pragma unroll
    for (int o = 16; o > 0; o >>= 1) sq += __shfl_xor_sync(0xffffffffu, sq, o);
    if ((tid & 31) == 0) s_red[tid >> 5] = sq;
    __syncthreads();
    const float tot   = s_red[0] + s_red[1] + s_red[2] + s_red[3];
    const float scale = s_amp / (sqrtf(tot) + 1e-8f);

    #pragma unroll
    for (int q = 0; q < 4; q++)
        g_wave[e * ATOM_SIZE + tid + q * 128] = w[q] * scale;
}

// ---------------- K3: deterministic gather of shifted waveforms ---------------
__global__ void gather_kernel(float* __restrict__ out)
{
    __shared__ int ps[N_EVENTS];
    const int tid = threadIdx.x;                 // 256 threads
    const int t0  = blockIdx.x * 256;
    const int t   = t0 + tid;

    if (tid < N_EVENTS) ps[tid] = g_pos[tid];
    __syncthreads();

    float acc = 0.0f;
    // fixed event order -> bit-deterministic float accumulation (no atomics)
    #pragma unroll 4
    for (int e = 0; e < N_EVENTS; e++) {
        const int p = ps[e];
        // event e covers [p, p+512); block covers [t0, t0+256)  (uniform test)
        if (p < t0 + 256 && p + ATOM_SIZE > t0) {
            const unsigned off = (unsigned)(t - p);
            if (off < (unsigned)ATOM_SIZE) acc += g_wave[e * ATOM_SIZE + off];
        }
    }
    out[t] = acc;
}

// ---------------- launch -------------------------------------------------------
extern "C" void kernel_launch(void* const* d_in, const int* in_sizes, int n_in,
                              void* d_out, int out_size)
{
    // Robust input mapping by element count (all sizes unique except the two 16s,
    // where dict order gives base_latent before to_amp_W).
    const float *base_latent = nullptr, *Wt = nullptr, *Ws = nullptr, *bs = nullptr;
    const float *atoms = nullptr, *Wa = nullptr, *ba = nullptr, *Wamp = nullptr, *bamp = nullptr;
    for (int i = 0; i < n_in; i++) {
        const int s = in_sizes[i];
        const float* p = (const float*)d_in[i];
        switch (s) {
            case LAYERS * 68 * LATENT:  Wt = p;    break;   // 7616
            case LAYERS * 32 * LATENT:  Ws = p;    break;   // 3584
            case LAYERS * 32:           bs = p;    break;   // 224
            case N_ATOMS * ATOM_SIZE:   atoms = p; break;   // 16384
            case N_ATOMS * LATENT:      Wa = p;    break;   // 512
            case N_ATOMS:               ba = p;    break;   // 32
            case 1:                     bamp = p;  break;   // 1
            case LATENT:                                    // 16, twice
                if (!base_latent) base_latent = p; else Wamp = p;
                break;
            default: break;
        }
    }

    float* out = (float*)d_out;

    tree_kernel<<<1, 256>>>(base_latent, Wt, Ws, bs);
    wave_kernel<<<N_EVENTS, 128>>>(atoms, Wa, ba, Wamp, bamp);
    gather_kernel<<<N_SAMPLES / 256, 256>>>(out);
    (void)out_size;
}

// round 5
// speedup vs baseline: 2.0398x; 2.0398x over previous
#include <cuda_runtime.h>
#include <math.h>

#define N_SAMPLES 131072
#define N_EVENTS  128
#define N_ATOMS   32
#define ATOM_SIZE 512
#define LATENT    16
#define TIME_DIM  17
#define LAYERS    7

// ---------------- device-global scratch (no allocation allowed) ----------------
__device__ float g_xf[N_EVENTS * LATENT];            // final latent per event
__device__ int   g_pos[N_EVENTS];                    // dirac shift per event
__device__ float g_wave[N_EVENTS * ATOM_SIZE];       // pre-scaled waveforms

// 16-term dot product, serial FMA chain in ascending index order.
// EXACTLY the same association order as the R3 passing kernel (v=0; v+=x[d]*w[d])
// so all 128 argmax bit decisions are bit-identical.
__device__ __forceinline__ float dot16(float4 w0, float4 w1, float4 w2, float4 w3,
                                       float4 x0, float4 x1, float4 x2, float4 x3,
                                       float init)
{
    float v = init;
    v = fmaf(x0.x, w0.x, v); v = fmaf(x0.y, w0.y, v);
    v = fmaf(x0.z, w0.z, v); v = fmaf(x0.w, w0.w, v);
    v = fmaf(x1.x, w1.x, v); v = fmaf(x1.y, w1.y, v);
    v = fmaf(x1.z, w1.z, v); v = fmaf(x1.w, w1.w, v);
    v = fmaf(x2.x, w2.x, v); v = fmaf(x2.y, w2.y, v);
    v = fmaf(x2.z, w2.z, v); v = fmaf(x2.w, w2.w, v);
    v = fmaf(x3.x, w3.x, v); v = fmaf(x3.y, w3.y, v);
    v = fmaf(x3.z, w3.z, v); v = fmaf(x3.w, w3.w, v);
    return v;
}

// ---------------- K1: binary tree, fully shared-memory resident ----------------
// 128 threads. Lane j owns one output row per layer:
//   j in [0,68)   : time-offset row  (child c = j/34, r = j%34 = t*2+s)
//   j in [68,100) : latent split row (child = (j-68)>>4, slot = (j-68)&15)
// Weight row lives in registers; the e-sweep reads x[e] via broadcast LDS.128.
__global__ void tree_kernel(const float* __restrict__ base_latent,
                            const float* __restrict__ Wt,   // (7, 68, 16)
                            const float* __restrict__ Ws,   // (7, 32, 16)
                            const float* __restrict__ bs)   // (7, 32)
{
    extern __shared__ float sm[];
    float* sx = sm;                              // 2 x (128*16)  ping-pong latent
    float* st = sm + 2 * N_EVENTS * LATENT;      // 2 x (128*34)  ping-pong times

    const int tid = threadIdx.x;                 // 128 threads

    if (tid < LATENT)       sx[tid] = base_latent[tid];
    if (tid < TIME_DIM * 2) st[tid] = 0.0f;
    __syncthreads();

    const bool is_time = (tid < 68);
    const bool is_lat  = (tid >= 68) && (tid < 100);
    const int  c  = tid / 34;                    // time: child index
    const int  r  = tid % 34;                    // time: (t*2 + s)
    const int  jl = tid - 68;                    // latent row
    const int  ch = jl >> 4;                     // latent: child index
    const int  sl = jl & 15;                     // latent: slot

    for (int i = 0; i < LAYERS; i++) {
        // ---- load this layer's weight row into registers (4 x LDG.128) ----
        float4 w0 = {0,0,0,0}, w1 = {0,0,0,0}, w2 = {0,0,0,0}, w3 = {0,0,0,0};
        float  bias = 0.0f;
        if (is_time) {
            const float4* wp = (const float4*)(Wt + (size_t)(i * 68 + tid) * LATENT);
            w0 = wp[0]; w1 = wp[1]; w2 = wp[2]; w3 = wp[3];
        } else if (is_lat) {
            const float4* wp = (const float4*)(Ws + (size_t)(i * 32 + jl) * LATENT);
            w0 = wp[0]; w1 = wp[1]; w2 = wp[2]; w3 = wp[3];
            bias = bs[i * 32 + jl];
        }

        const int n = 1 << i;
        const float* xA = sx + (i & 1) * (N_EVENTS * LATENT);
        float*       xB = sx + ((i & 1) ^ 1) * (N_EVENTS * LATENT);
        const float* tA = st + (i & 1) * (N_EVENTS * 34);
        float*       tB = st + ((i & 1) ^ 1) * (N_EVENTS * 34);

        if (is_time) {
            #pragma unroll 4
            for (int e = 0; e < n; e++) {
                const float4* xp = (const float4*)(xA + e * LATENT);
                float4 x0 = xp[0], x1 = xp[1], x2 = xp[2], x3 = xp[3];
                const float v = dot16(w0, w1, w2, w3, x0, x1, x2, x3, 0.0f);
                tB[(2 * e + c) * 34 + r] = tA[e * 34 + r] + v;
            }
        } else if (is_lat) {
            #pragma unroll 4
            for (int e = 0; e < n; e++) {
                const float4* xp = (const float4*)(xA + e * LATENT);
                float4 x0 = xp[0], x1 = xp[1], x2 = xp[2], x3 = xp[3];
                const float v = dot16(w0, w1, w2, w3, x0, x1, x2, x3, bias);
                xB[(2 * e + ch) * LATENT + sl] = v;
            }
        }
        __syncthreads();
    }

    // LAYERS = 7 (odd) -> final buffers live in parity 1
    const float* xF = sx + (N_EVENTS * LATENT);
    const float* tF = st + (N_EVENTS * 34);

    // export final latents to global for wave_kernel
    for (int k = tid; k < N_EVENTS * LATENT; k += blockDim.x)
        g_xf[k] = xF[k];

    // argmax over size-2 axis per time dim; ties -> index 0 (strict >), MSB first
    {
        const int e = tid;   // 128 threads == 128 events
        int p = 0;
        #pragma unroll
        for (int t = 0; t < TIME_DIM; t++) {
            const int bit = tF[e * 34 + t * 2 + 1] > tF[e * 34 + t * 2 + 0];
            p |= bit << (TIME_DIM - 1 - t);
        }
        g_pos[e] = p;
    }
}

// ---------------- K2: per-event waveform (coeffs, window, norm, amp) -----------
__global__ void wave_kernel(const float* __restrict__ atoms,   // (32, 512)
                            const float* __restrict__ Wa,      // (32, 16)
                            const float* __restrict__ ba,      // (32,)
                            const float* __restrict__ Wamp,    // (1, 16)
                            const float* __restrict__ bamp)    // (1,)
{
    __shared__ float cs[N_ATOMS];
    __shared__ float s_amp;
    __shared__ float s_red[4];

    const int e   = blockIdx.x;
    const int tid = threadIdx.x;          // 128 threads
    const float* xe = g_xf + e * LATENT;

    if (tid < N_ATOMS) {
        float v = ba[tid];
        #pragma unroll
        for (int d = 0; d < LATENT; d++) v += xe[d] * Wa[tid * LATENT + d];
        cs[tid] = v;
    }
    if (tid == N_ATOMS) {
        float v = bamp[0];
        #pragma unroll
        for (int d = 0; d < LATENT; d++) v += xe[d] * Wamp[d];
        s_amp = v;
    }
    __syncthreads();

    float w[4];
    float sq = 0.0f;
    #pragma unroll
    for (int q = 0; q < 4; q++) {
        const int j = tid + q * 128;
        float v = 0.0f;
        #pragma unroll
        for (int k = 0; k < N_ATOMS; k++) v += cs[k] * atoms[k * ATOM_SIZE + j];
        // Hamming window: 0.54 - 0.46*cos(2*pi*j/512)
        const float win = 0.54f - 0.46f * cospif((float)j * (1.0f / 256.0f));
        v *= win;
        w[q] = v;
        sq += v * v;
    }

    // block reduce sum of squares (4 warps)
    #pragma unroll
    for (int o = 16; o > 0; o >>= 1) sq += __shfl_xor_sync(0xffffffffu, sq, o);
    if ((tid & 31) == 0) s_red[tid >> 5] = sq;
    __syncthreads();
    const float tot   = s_red[0] + s_red[1] + s_red[2] + s_red[3];
    const float scale = s_amp / (sqrtf(tot) + 1e-8f);

    #pragma unroll
    for (int q = 0; q < 4; q++)
        g_wave[e * ATOM_SIZE + tid + q * 128] = w[q] * scale;
}

// ---------------- K3: deterministic gather of shifted waveforms ---------------
__global__ void gather_kernel(float* __restrict__ out)
{
    __shared__ int ps[N_EVENTS];
    const int tid = threadIdx.x;                 // 256 threads
    const int t0  = blockIdx.x * 256;
    const int t   = t0 + tid;

    if (tid < N_EVENTS) ps[tid] = g_pos[tid];
    __syncthreads();

    float acc = 0.0f;
    // fixed event order -> bit-deterministic float accumulation (no atomics)
    #pragma unroll 4
    for (int e = 0; e < N_EVENTS; e++) {
        const int p = ps[e];
        if (p < t0 + 256 && p + ATOM_SIZE > t0) {
            const unsigned off = (unsigned)(t - p);
            if (off < (unsigned)ATOM_SIZE) acc += g_wave[e * ATOM_SIZE + off];
        }
    }
    out[t] = acc;
}

// ---------------- launch -------------------------------------------------------
extern "C" void kernel_launch(void* const* d_in, const int* in_sizes, int n_in,
                              void* d_out, int out_size)
{
    // Robust input mapping by element count (all sizes unique except the two 16s,
    // where dict order gives base_latent before to_amp_W).
    const float *base_latent = nullptr, *Wt = nullptr, *Ws = nullptr, *bs = nullptr;
    const float *atoms = nullptr, *Wa = nullptr, *ba = nullptr, *Wamp = nullptr, *bamp = nullptr;
    for (int i = 0; i < n_in; i++) {
        const int s = in_sizes[i];
        const float* p = (const float*)d_in[i];
        switch (s) {
            case LAYERS * 68 * LATENT:  Wt = p;    break;   // 7616
            case LAYERS * 32 * LATENT:  Ws = p;    break;   // 3584
            case LAYERS * 32:           bs = p;    break;   // 224
            case N_ATOMS * ATOM_SIZE:   atoms = p; break;   // 16384
            case N_ATOMS * LATENT:      Wa = p;    break;   // 512
            case N_ATOMS:               ba = p;    break;   // 32
            case 1:                     bamp = p;  break;   // 1
            case LATENT:                                    // 16, twice
                if (!base_latent) base_latent = p; else Wamp = p;
                break;
            default: break;
        }
    }

    float* out = (float*)d_out;

    // tree needs 51.2 KB dynamic smem (2x latent ping-pong + 2x time ping-pong)
    const int tree_smem = (2 * N_EVENTS * LATENT + 2 * N_EVENTS * 34) * (int)sizeof(float);
    cudaFuncSetAttribute(tree_kernel, cudaFuncAttributeMaxDynamicSharedMemorySize, tree_smem);

    tree_kernel<<<1, 128, tree_smem>>>(base_latent, Wt, Ws, bs);
    wave_kernel<<<N_EVENTS, 128>>>(atoms, Wa, ba, Wamp, bamp);
    gather_kernel<<<N_SAMPLES / 256, 256>>>(out);
    (void)out_size;
}